// round 1
// baseline (speedup 1.0000x reference)
#include <cuda_runtime.h>
#include <math.h>

// Problem constants
#define BB   2
#define FF   5
#define CC   256
#define HH   64
#define WW   64
#define HNN  8
#define DPC  128          // dp = C/2
#define HDD  16           // head dim
#define HWS  4096         // H*W
#define TOK  40960        // B*F*H*W

// qkv buffer: [dir(2)][b(2)][n(8)][l(64)][sel(3)][f(5)][1024]
#define QKV_HALF (2*8*64*3*5*1024)   // 15,728,640 floats

// Scratch (static device memory; no allocations allowed)
__device__ float g_xn [TOK*256];      // LN1 output, token-major
__device__ float g_xT [TOK*256];      // x, token-major (for residual)
__device__ float g_qkv[2*QKV_HALF];
__device__ float g_ao [TOK*256];      // attention output, token-major
__device__ float g_y  [TOK*256];      // y = proj + x (this is "t" in reference)
__device__ float g_tn [TOK*256];      // LN2 output
__device__ float g_hid[TOK*1024];     // MLP hidden

// ---------------------------------------------------------------------------
// LN1: x (B,F,C,H,W) -> xn token-major (t,256); also writes x token-major.
// Block: 256 threads, handles 32 consecutive hw positions for one (b,f).
// ---------------------------------------------------------------------------
__global__ __launch_bounds__(256) void ln1_kernel(
    const float* __restrict__ x,
    const float* __restrict__ gam,
    const float* __restrict__ bet)
{
    __shared__ float sm[256][33];
    __shared__ float psum[8][32], psq[8][32];
    __shared__ float mu[32], rs[32];

    int bf  = blockIdx.y;
    int hw0 = blockIdx.x * 32;
    int tid = threadIdx.x;
    int tx  = tid & 31, ty = tid >> 5;

    const float* xp = x + (size_t)bf * CC * HWS;
    #pragma unroll
    for (int c0 = 0; c0 < 256; c0 += 8) {
        int c = c0 + ty;
        sm[c][tx] = xp[(size_t)c * HWS + hw0 + tx];
    }
    __syncthreads();

    float s = 0.f, sq = 0.f;
    #pragma unroll
    for (int k = 0; k < 32; k++) {
        float v = sm[ty * 32 + k][tx];
        s += v; sq += v * v;
    }
    psum[ty][tx] = s; psq[ty][tx] = sq;
    __syncthreads();

    if (ty == 0) {
        float S = 0.f, Q = 0.f;
        #pragma unroll
        for (int k = 0; k < 8; k++) { S += psum[k][tx]; Q += psq[k][tx]; }
        float m   = S * (1.f / 256.f);
        float var = Q * (1.f / 256.f) - m * m;
        mu[tx] = m;
        rs[tx] = rsqrtf(var + 1e-5f);
    }
    __syncthreads();

    int tokl = tid >> 3, cg = tid & 7;
    int tok  = bf * HWS + hw0 + tokl;
    float m = mu[tokl], r = rs[tokl];
    size_t rowoff = (size_t)tok * 256;
    #pragma unroll
    for (int k = 0; k < 32; k++) {
        int c = k * 8 + cg;
        float v = sm[c][tokl];
        g_xn[rowoff + c] = (v - m) * r * gam[c] + bet[c];
        g_xT[rowoff + c] = v;
    }
}

// ---------------------------------------------------------------------------
// Shared 128x128 GEMM core: C[m][n] = sum_k A[m][k] * B[n][k]  (NT form)
// 256 threads, 8x8 per thread, BK=16. Requires M%128==0, N%128==0, K%16==0.
// ---------------------------------------------------------------------------
__device__ __forceinline__ void gemm128(
    const float* __restrict__ A, int lda,
    const float* __restrict__ Bm, int ldb,
    int K, int m0, int n0,
    float (&acc)[8][8])
{
    __shared__ __align__(16) float As[16][132];
    __shared__ __align__(16) float Bs[16][132];
    int tid = threadIdx.x;
    int tm = tid >> 4, tn = tid & 15;

    #pragma unroll
    for (int i = 0; i < 8; i++)
        #pragma unroll
        for (int j = 0; j < 8; j++) acc[i][j] = 0.f;

    for (int k0 = 0; k0 < K; k0 += 16) {
        #pragma unroll
        for (int it = 0; it < 2; it++) {
            int idx = tid * 2 + it;          // 0..511
            int row = idx >> 2, q = idx & 3;
            float4 va = *reinterpret_cast<const float4*>(
                &A[(size_t)(m0 + row) * lda + k0 + q * 4]);
            As[q*4+0][row] = va.x; As[q*4+1][row] = va.y;
            As[q*4+2][row] = va.z; As[q*4+3][row] = va.w;
            float4 vb = *reinterpret_cast<const float4*>(
                &Bm[(size_t)(n0 + row) * ldb + k0 + q * 4]);
            Bs[q*4+0][row] = vb.x; Bs[q*4+1][row] = vb.y;
            Bs[q*4+2][row] = vb.z; Bs[q*4+3][row] = vb.w;
        }
        __syncthreads();
        #pragma unroll
        for (int k = 0; k < 16; k++) {
            float a[8], bv[8];
            *reinterpret_cast<float4*>(&a[0])  = *reinterpret_cast<const float4*>(&As[k][tm*8]);
            *reinterpret_cast<float4*>(&a[4])  = *reinterpret_cast<const float4*>(&As[k][tm*8+4]);
            *reinterpret_cast<float4*>(&bv[0]) = *reinterpret_cast<const float4*>(&Bs[k][tn*8]);
            *reinterpret_cast<float4*>(&bv[4]) = *reinterpret_cast<const float4*>(&Bs[k][tn*8+4]);
            #pragma unroll
            for (int i = 0; i < 8; i++)
                #pragma unroll
                for (int j = 0; j < 8; j++)
                    acc[i][j] = fmaf(a[i], bv[j], acc[i][j]);
        }
        __syncthreads();
    }
}

// ---------------------------------------------------------------------------
// QKV GEMM: xn[:, branch*128 : +128] @ w^T + b, scattered into attention layout
// grid: (3 n-tiles, 320 m-tiles, 2 branches)
// ---------------------------------------------------------------------------
__global__ __launch_bounds__(256) void qkv_gemm(
    const float* __restrict__ wh, const float* __restrict__ bh,
    const float* __restrict__ wv, const float* __restrict__ bv)
{
    int branch = blockIdx.z;
    const float* Wm   = branch ? wv : wh;
    const float* bias = branch ? bv : bh;
    const float* A    = g_xn + branch * 128;

    int m0 = blockIdx.y * 128, n0 = blockIdx.x * 128;
    float acc[8][8];
    gemm128(A, 256, Wm, 128, 128, m0, n0, acc);

    int tm = threadIdx.x >> 4, tn = threadIdx.x & 15;
    float* dst = g_qkv + (size_t)branch * QKV_HALF;
    #pragma unroll
    for (int i = 0; i < 8; i++) {
        int t  = m0 + tm * 8 + i;
        int bf = t >> 12, hw = t & 4095;
        int h = hw >> 6, w = hw & 63;
        int b = bf / 5, f = bf - b * 5;
        int l  = branch ? w : h;
        int dd = branch ? h : w;
        #pragma unroll
        for (int j = 0; j < 8; j++) {
            int o   = n0 + tn * 8 + j;
            int sel = o >> 7, rr = o & 127;
            int n = rr >> 4, d = rr & 15;
            size_t idx = ((((size_t)(b * 8 + n) * 64 + l) * 3 + sel) * 5 + f) * 1024
                         + dd * 16 + d;
            dst[idx] = acc[i][j] + bias[o];
        }
    }
}

// ---------------------------------------------------------------------------
// Attention: per (dir, b, head, line): Q,K,V are [5][1024]; S=QK^T/32,
// softmax over 5, O=PV. Writes into g_ao token-major (concat h|v on channels).
// ---------------------------------------------------------------------------
__global__ __launch_bounds__(256) void attn_kernel()
{
    int id   = blockIdx.x;            // 0..2047
    int dir  = id >> 10;
    int bidx = id & 1023;
    int b = bidx >> 9;
    int n = (bidx >> 6) & 7;
    int l = bidx & 63;

    const float* base = g_qkv + (size_t)dir * QKV_HALF
                      + ((size_t)((b * 8 + n) * 64 + l) * 3) * 5 * 1024;
    const float* Q  = base;
    const float* Kp = base + 5 * 1024;
    const float* V  = base + 10 * 1024;

    int tid = threadIdx.x;
    int d0  = tid * 4;

    float4 q[5], k[5];
    #pragma unroll
    for (int i = 0; i < 5; i++) {
        q[i] = *reinterpret_cast<const float4*>(Q  + i * 1024 + d0);
        k[i] = *reinterpret_cast<const float4*>(Kp + i * 1024 + d0);
    }
    float p[25];
    #pragma unroll
    for (int i = 0; i < 5; i++)
        #pragma unroll
        for (int j = 0; j < 5; j++) {
            float4 a = q[i], c = k[j];
            p[i*5+j] = a.x*c.x + a.y*c.y + a.z*c.z + a.w*c.w;
        }

    __shared__ float red[25][8];
    #pragma unroll
    for (int e = 0; e < 25; e++) {
        float v = p[e];
        #pragma unroll
        for (int off = 16; off; off >>= 1) v += __shfl_down_sync(0xffffffffu, v, off);
        if ((tid & 31) == 0) red[e][tid >> 5] = v;
    }
    __syncthreads();

    __shared__ float P[5][5];
    if (tid < 5) {
        float srow[5];
        float mx = -1e30f;
        #pragma unroll
        for (int j = 0; j < 5; j++) {
            float s = 0.f;
            #pragma unroll
            for (int wdx = 0; wdx < 8; wdx++) s += red[tid*5+j][wdx];
            s *= (1.f / 32.f);
            srow[j] = s; mx = fmaxf(mx, s);
        }
        float se = 0.f;
        #pragma unroll
        for (int j = 0; j < 5; j++) { srow[j] = __expf(srow[j] - mx); se += srow[j]; }
        float inv = 1.f / se;
        #pragma unroll
        for (int j = 0; j < 5; j++) P[tid][j] = srow[j] * inv;
    }
    __syncthreads();

    float4 o[5];
    #pragma unroll
    for (int i = 0; i < 5; i++) o[i] = make_float4(0.f, 0.f, 0.f, 0.f);
    #pragma unroll
    for (int j = 0; j < 5; j++) {
        float4 v = *reinterpret_cast<const float4*>(V + j * 1024 + d0);
        #pragma unroll
        for (int i = 0; i < 5; i++) {
            float pij = P[i][j];
            o[i].x = fmaf(pij, v.x, o[i].x);
            o[i].y = fmaf(pij, v.y, o[i].y);
            o[i].z = fmaf(pij, v.z, o[i].z);
            o[i].w = fmaf(pij, v.w, o[i].w);
        }
    }

    int wc = d0 >> 4, dlo = d0 & 15;       // dlo in {0,4,8,12}
    int hw = dir ? (wc * 64 + l) : (l * 64 + wc);
    int c  = dir ? (128 + n * 16 + dlo) : (n * 16 + dlo);
    #pragma unroll
    for (int fi = 0; fi < 5; fi++) {
        size_t tok = (size_t)(b * 5 + fi) * 4096 + hw;
        *reinterpret_cast<float4*>(g_ao + tok * 256 + c) = o[fi];
    }
}

// ---------------------------------------------------------------------------
// Output projection + residual:  y = ao @ wf^T + bf + x   (token-major)
// ---------------------------------------------------------------------------
__global__ __launch_bounds__(256) void proj_gemm(
    const float* __restrict__ wf, const float* __restrict__ bfp)
{
    int m0 = blockIdx.y * 128, n0 = blockIdx.x * 128;
    float acc[8][8];
    gemm128(g_ao, 256, wf, 256, 256, m0, n0, acc);

    int tm = threadIdx.x >> 4, tn = threadIdx.x & 15;
    #pragma unroll
    for (int i = 0; i < 8; i++) {
        int t = m0 + tm * 8 + i;
        size_t rowoff = (size_t)t * 256;
        #pragma unroll
        for (int j = 0; j < 8; j += 4) {
            int o = n0 + tn * 8 + j;
            float4 xv = *reinterpret_cast<const float4*>(g_xT + rowoff + o);
            float4 bv = *reinterpret_cast<const float4*>(bfp + o);
            float4 r;
            r.x = acc[i][j+0] + bv.x + xv.x;
            r.y = acc[i][j+1] + bv.y + xv.y;
            r.z = acc[i][j+2] + bv.z + xv.z;
            r.w = acc[i][j+3] + bv.w + xv.w;
            *reinterpret_cast<float4*>(g_y + rowoff + o) = r;
        }
    }
}

// ---------------------------------------------------------------------------
// LN2 over g_y rows (contiguous 256) -> g_tn. One warp per token.
// ---------------------------------------------------------------------------
__global__ __launch_bounds__(256) void ln2_kernel(
    const float* __restrict__ gam, const float* __restrict__ bet)
{
    int t    = blockIdx.x * 8 + (threadIdx.x >> 5);
    int lane = threadIdx.x & 31;
    const float* row = g_y + (size_t)t * 256;
    int c = lane * 4;

    float4 v0 = *reinterpret_cast<const float4*>(row + c);
    float4 v1 = *reinterpret_cast<const float4*>(row + 128 + c);
    float s  = v0.x + v0.y + v0.z + v0.w + v1.x + v1.y + v1.z + v1.w;
    float sq = v0.x*v0.x + v0.y*v0.y + v0.z*v0.z + v0.w*v0.w
             + v1.x*v1.x + v1.y*v1.y + v1.z*v1.z + v1.w*v1.w;
    #pragma unroll
    for (int off = 16; off; off >>= 1) {
        s  += __shfl_xor_sync(0xffffffffu, s,  off);
        sq += __shfl_xor_sync(0xffffffffu, sq, off);
    }
    float m = s * (1.f / 256.f);
    float r = rsqrtf(sq * (1.f / 256.f) - m * m + 1e-5f);

    float* out = g_tn + (size_t)t * 256;
    float4 g0 = *reinterpret_cast<const float4*>(gam + c);
    float4 b0 = *reinterpret_cast<const float4*>(bet + c);
    float4 g1 = *reinterpret_cast<const float4*>(gam + 128 + c);
    float4 b1 = *reinterpret_cast<const float4*>(bet + 128 + c);
    float4 r0, r1;
    r0.x = (v0.x - m) * r * g0.x + b0.x;
    r0.y = (v0.y - m) * r * g0.y + b0.y;
    r0.z = (v0.z - m) * r * g0.z + b0.z;
    r0.w = (v0.w - m) * r * g0.w + b0.w;
    r1.x = (v1.x - m) * r * g1.x + b1.x;
    r1.y = (v1.y - m) * r * g1.y + b1.y;
    r1.z = (v1.z - m) * r * g1.z + b1.z;
    r1.w = (v1.w - m) * r * g1.w + b1.w;
    *reinterpret_cast<float4*>(out + c)       = r0;
    *reinterpret_cast<float4*>(out + 128 + c) = r1;
}

// ---------------------------------------------------------------------------
// MLP GEMM1 + exact GELU:  hid = gelu(tn @ w1^T + b1)
// ---------------------------------------------------------------------------
__global__ __launch_bounds__(256) void mlp1_gemm(
    const float* __restrict__ w1, const float* __restrict__ b1)
{
    int m0 = blockIdx.y * 128, n0 = blockIdx.x * 128;
    float acc[8][8];
    gemm128(g_tn, 256, w1, 256, 256, m0, n0, acc);

    int tm = threadIdx.x >> 4, tn = threadIdx.x & 15;
    #pragma unroll
    for (int i = 0; i < 8; i++) {
        int t = m0 + tm * 8 + i;
        size_t rowoff = (size_t)t * 1024;
        #pragma unroll
        for (int j = 0; j < 8; j += 4) {
            int o = n0 + tn * 8 + j;
            float4 bv = *reinterpret_cast<const float4*>(b1 + o);
            float4 r;
            float h0 = acc[i][j+0] + bv.x;
            float h1 = acc[i][j+1] + bv.y;
            float h2 = acc[i][j+2] + bv.z;
            float h3 = acc[i][j+3] + bv.w;
            r.x = 0.5f * h0 * (1.f + erff(h0 * 0.70710678118654752f));
            r.y = 0.5f * h1 * (1.f + erff(h1 * 0.70710678118654752f));
            r.z = 0.5f * h2 * (1.f + erff(h2 * 0.70710678118654752f));
            r.w = 0.5f * h3 * (1.f + erff(h3 * 0.70710678118654752f));
            *reinterpret_cast<float4*>(g_hid + rowoff + o) = r;
        }
    }
}

// ---------------------------------------------------------------------------
// MLP GEMM2 + residual + transposed store:
// out[b,f,c,h,w] = y[t][c] + hid[t] @ w2^T[c] + b2[c]
// ---------------------------------------------------------------------------
__global__ __launch_bounds__(256) void mlp2_gemm(
    const float* __restrict__ w2, const float* __restrict__ b2,
    float* __restrict__ out)
{
    int m0 = blockIdx.y * 128, n0 = blockIdx.x * 128;
    float acc[8][8];
    gemm128(g_hid, 1024, w2, 1024, 1024, m0, n0, acc);

    int tm = threadIdx.x >> 4, tn = threadIdx.x & 15;
    #pragma unroll
    for (int i = 0; i < 8; i++) {
        int t  = m0 + tm * 8 + i;
        int bf = t >> 12, hw = t & 4095;
        size_t rowoff = (size_t)t * 256;
        #pragma unroll
        for (int j = 0; j < 8; j += 4) {
            int o = n0 + tn * 8 + j;
            float4 yv = *reinterpret_cast<const float4*>(g_y + rowoff + o);
            float4 bv = *reinterpret_cast<const float4*>(b2 + o);
            out[((size_t)bf * 256 + o + 0) * 4096 + hw] = acc[i][j+0] + bv.x + yv.x;
            out[((size_t)bf * 256 + o + 1) * 4096 + hw] = acc[i][j+1] + bv.y + yv.y;
            out[((size_t)bf * 256 + o + 2) * 4096 + hw] = acc[i][j+2] + bv.z + yv.z;
            out[((size_t)bf * 256 + o + 3) * 4096 + hw] = acc[i][j+3] + bv.w + yv.w;
        }
    }
}

// ---------------------------------------------------------------------------
extern "C" void kernel_launch(void* const* d_in, const int* in_sizes, int n_in,
                              void* d_out, int out_size)
{
    const float* x     = (const float*)d_in[0];
    const float* ln1_g = (const float*)d_in[1];
    const float* ln1_b = (const float*)d_in[2];
    const float* wh    = (const float*)d_in[3];
    const float* bh    = (const float*)d_in[4];
    const float* wv    = (const float*)d_in[5];
    const float* bv    = (const float*)d_in[6];
    const float* wf    = (const float*)d_in[7];
    const float* bf    = (const float*)d_in[8];
    const float* ln2_g = (const float*)d_in[9];
    const float* ln2_b = (const float*)d_in[10];
    const float* w1    = (const float*)d_in[11];
    const float* b1    = (const float*)d_in[12];
    const float* w2    = (const float*)d_in[13];
    const float* b2    = (const float*)d_in[14];
    float* out = (float*)d_out;

    ln1_kernel<<<dim3(128, 10), 256>>>(x, ln1_g, ln1_b);
    qkv_gemm  <<<dim3(3, 320, 2), 256>>>(wh, bh, wv, bv);
    attn_kernel<<<2048, 256>>>();
    proj_gemm <<<dim3(2, 320), 256>>>(wf, bf);
    ln2_kernel<<<5120, 256>>>(ln2_g, ln2_b);
    mlp1_gemm <<<dim3(8, 320), 256>>>(w1, b1);
    mlp2_gemm <<<dim3(2, 320), 256>>>(w2, b2, out);
}

// round 3
// speedup vs baseline: 3.9528x; 3.9528x over previous
#include <cuda_runtime.h>
#include <cuda_bf16.h>
#include <math.h>
#include <cstdint>

// ---------------------------------------------------------------------------
// Problem constants
// ---------------------------------------------------------------------------
#define HWS  4096         // H*W
#define TOK  40960        // B*F*H*W
#define QKV_HALF (TOK*384)

// ---------------------------------------------------------------------------
// Static device scratch
// ---------------------------------------------------------------------------
__device__ __nv_bfloat16 g_xn_bf [TOK*256];    // LN1 out (bf16, token-major)
__device__ float         g_xT    [TOK*256];    // x token-major fp32 (residual)
__device__ __nv_bfloat16 g_qkv_bf[2*QKV_HALF]; // qkv token-major [branch][t][384]
__device__ __nv_bfloat16 g_ao_bf [TOK*256];    // attention out (bf16 token-major)
__device__ float         g_y     [TOK*256];    // y = proj + x (fp32)
__device__ __nv_bfloat16 g_tn_bf [TOK*256];    // LN2 out (bf16)
__device__ __nv_bfloat16 g_hid_bf[TOK*1024];   // MLP hidden (bf16)
// bf16 weight copies
__device__ __nv_bfloat16 g_wh[384*128];
__device__ __nv_bfloat16 g_wv[384*128];
__device__ __nv_bfloat16 g_wf[256*256];
__device__ __nv_bfloat16 g_w1[1024*256];
__device__ __nv_bfloat16 g_w2[256*1024];

#define SMEM_SWIZZLE_128B(byte_offset) \
    ((byte_offset) ^ (((byte_offset) >> 3) & 0x70))

// Dynamic smem: GEMM stages 2 x (16KB A + 16KB B) = 64KB.
// Epilogue reuse: fp32 tile [128][132] = 67584B (proj/mlp2),
//                 bf16 tile [128][136] = 34816B (qkv/mlp1).
#define SMEM_DYN 67584

// ---------------------------------------------------------------------------
// m16n8k16 bf16 MMA (sm_80+ baseline ISA — legal at compute_103)
// ---------------------------------------------------------------------------
__device__ __forceinline__ void mma16816(float d[4], const uint32_t a[4],
                                         uint32_t b0, uint32_t b1)
{
    asm volatile(
        "mma.sync.aligned.m16n8k16.row.col.f32.bf16.bf16.f32 "
        "{%0,%1,%2,%3},{%4,%5,%6,%7},{%8,%9},{%0,%1,%2,%3};"
        : "+f"(d[0]), "+f"(d[1]), "+f"(d[2]), "+f"(d[3])
        : "r"(a[0]), "r"(a[1]), "r"(a[2]), "r"(a[3]), "r"(b0), "r"(b1));
}

// ---------------------------------------------------------------------------
// Warp-MMA GEMM: acc[fm][fn][4] += A[m0+*,k] * B[n0+*,k]^T, bf16 in fp32 out.
// Tile 128x128, 8 warps (warp: 64m x 32n), K chunks of 64, double-buffered.
// Thread mapping (per mma frag): g = lane>>2, tq = lane&3.
//   value acc[fm][fn][i]: m = wm+fm*16+g+8*(i>>1), n = wn+fn*8+tq*2+(i&1)
// ---------------------------------------------------------------------------
__device__ __forceinline__ void wgemm(
    const __nv_bfloat16* __restrict__ A, int lda,
    const __nv_bfloat16* __restrict__ B, int ldb,
    int m0, int n0, int nchunks, char* sm,
    float (&acc)[4][4][4])
{
    const int tid = threadIdx.x;
    const int lane = tid & 31;
    const int w = tid >> 5;
    const int wm = (w & 1) * 64;
    const int wn = (w >> 1) * 32;
    const int g = lane >> 2, tq = lane & 3;
    const int r_ld = tid >> 3;      // 0..31
    const int cc_ld = tid & 7;      // 16B chunk within 128B row

    #pragma unroll
    for (int fm = 0; fm < 4; fm++)
        #pragma unroll
        for (int fn = 0; fn < 4; fn++)
            #pragma unroll
            for (int i = 0; i < 4; i++) acc[fm][fn][i] = 0.f;

    uint4 pf[8];

    auto fetch = [&](int c) {
        int k0 = c << 6;
        #pragma unroll
        for (int it = 0; it < 4; it++) {
            int r = it * 32 + r_ld;
            pf[it]     = *(const uint4*)(A + (size_t)(m0 + r) * lda + k0 + cc_ld * 8);
            pf[4 + it] = *(const uint4*)(B + (size_t)(n0 + r) * ldb + k0 + cc_ld * 8);
        }
    };
    auto store = [&](int s) {
        char* base = sm + s * 32768;
        #pragma unroll
        for (int it = 0; it < 4; it++) {
            uint32_t off = SMEM_SWIZZLE_128B((uint32_t)((it * 32 + r_ld) * 128 + cc_ld * 16));
            *(uint4*)(base + off)         = pf[it];
            *(uint4*)(base + 16384 + off) = pf[4 + it];
        }
    };
    auto compute = [&](int s) {
        const char* Ab = sm + s * 32768;
        const char* Bb = Ab + 16384;
        #pragma unroll
        for (int ks = 0; ks < 4; ks++) {
            int kb = ks * 32 + tq * 4;
            uint32_t a[4][4];
            #pragma unroll
            for (int fm = 0; fm < 4; fm++) {
                int r = wm + fm * 16 + g;
                a[fm][0] = *(const uint32_t*)(Ab + SMEM_SWIZZLE_128B((uint32_t)(r * 128 + kb)));
                a[fm][1] = *(const uint32_t*)(Ab + SMEM_SWIZZLE_128B((uint32_t)((r + 8) * 128 + kb)));
                a[fm][2] = *(const uint32_t*)(Ab + SMEM_SWIZZLE_128B((uint32_t)(r * 128 + kb + 16)));
                a[fm][3] = *(const uint32_t*)(Ab + SMEM_SWIZZLE_128B((uint32_t)((r + 8) * 128 + kb + 16)));
            }
            #pragma unroll
            for (int fn = 0; fn < 4; fn++) {
                int rn = wn + fn * 8 + g;
                uint32_t b0 = *(const uint32_t*)(Bb + SMEM_SWIZZLE_128B((uint32_t)(rn * 128 + kb)));
                uint32_t b1 = *(const uint32_t*)(Bb + SMEM_SWIZZLE_128B((uint32_t)(rn * 128 + kb + 16)));
                #pragma unroll
                for (int fm = 0; fm < 4; fm++)
                    mma16816(acc[fm][fn], a[fm], b0, b1);
            }
        }
    };

    fetch(0); store(0);
    __syncthreads();
    for (int c = 0; c < nchunks; c++) {
        if (c + 1 < nchunks) fetch(c + 1);
        compute(c & 1);
        if (c + 1 < nchunks) {
            store((c + 1) & 1);
            __syncthreads();
        }
    }
    __syncthreads();   // stages dead; smem reusable by epilogue
}

// ---------------------------------------------------------------------------
// LN1: x (B,F,C,H,W) -> g_xn_bf (bf16 token-major) + g_xT (fp32 token-major)
// ---------------------------------------------------------------------------
__global__ __launch_bounds__(256) void ln1_kernel(
    const float* __restrict__ x,
    const float* __restrict__ gam,
    const float* __restrict__ bet)
{
    __shared__ float sm[256][33];
    __shared__ float psum[8][32], psq[8][32];
    __shared__ float mu[32], rs[32];

    int bf  = blockIdx.y;
    int hw0 = blockIdx.x * 32;
    int tid = threadIdx.x;
    int tx  = tid & 31, ty = tid >> 5;

    const float* xp = x + (size_t)bf * 256 * HWS;
    #pragma unroll
    for (int c0 = 0; c0 < 256; c0 += 8) {
        int c = c0 + ty;
        sm[c][tx] = xp[(size_t)c * HWS + hw0 + tx];
    }
    __syncthreads();

    float s = 0.f, sq = 0.f;
    #pragma unroll
    for (int k = 0; k < 32; k++) {
        float v = sm[ty * 32 + k][tx];
        s += v; sq += v * v;
    }
    psum[ty][tx] = s; psq[ty][tx] = sq;
    __syncthreads();

    if (ty == 0) {
        float S = 0.f, Q = 0.f;
        #pragma unroll
        for (int k = 0; k < 8; k++) { S += psum[k][tx]; Q += psq[k][tx]; }
        float m   = S * (1.f / 256.f);
        float var = Q * (1.f / 256.f) - m * m;
        mu[tx] = m;
        rs[tx] = rsqrtf(var + 1e-5f);
    }
    __syncthreads();

    int tokl = tid >> 3, cg = tid & 7;
    int tok  = bf * HWS + hw0 + tokl;
    float m = mu[tokl], r = rs[tokl];
    size_t rowoff = (size_t)tok * 256;
    #pragma unroll
    for (int k = 0; k < 32; k++) {
        int c = k * 8 + cg;
        float v = sm[c][tokl];
        g_xn_bf[rowoff + c] = __float2bfloat16_rn((v - m) * r * gam[c] + bet[c]);
        g_xT[rowoff + c] = v;
    }
}

// ---------------------------------------------------------------------------
__global__ __launch_bounds__(256) void cvt_kernel(
    const float* __restrict__ src, __nv_bfloat16* __restrict__ dst, int n)
{
    int i = blockIdx.x * 256 + threadIdx.x;
    if (i < n) dst[i] = __float2bfloat16_rn(src[i]);
}

// ---------------------------------------------------------------------------
// QKV GEMM -> token-major g_qkv_bf[branch][t][384]
// ---------------------------------------------------------------------------
__global__ __launch_bounds__(256) void qkv_mm(
    const float* __restrict__ bh, const float* __restrict__ bv)
{
    extern __shared__ char dsm[];
    int branch = blockIdx.z;
    int m0 = blockIdx.y * 128, n0 = blockIdx.x * 128;
    const __nv_bfloat16* A = g_xn_bf + branch * 128;
    const __nv_bfloat16* W = branch ? g_wv : g_wh;
    const float* bias = branch ? bv : bh;

    float acc[4][4][4];
    wgemm(A, 256, W, 128, m0, n0, 2, dsm, acc);

    // stage bf16 tile [m][o], stride 136 bf16 (272B rows)
    const int lane = threadIdx.x & 31, w = threadIdx.x >> 5;
    const int wm = (w & 1) * 64, wn = (w >> 1) * 32;
    const int g = lane >> 2, tq = lane & 3;
    #pragma unroll
    for (int fm = 0; fm < 4; fm++)
        #pragma unroll
        for (int i2 = 0; i2 < 2; i2++) {
            int ml = wm + fm * 16 + g + i2 * 8;
            #pragma unroll
            for (int fn = 0; fn < 4; fn++) {
                int ol = wn + fn * 8 + tq * 2;
                int o  = n0 + ol;
                float v0 = acc[fm][fn][i2 * 2]     + __ldg(bias + o);
                float v1 = acc[fm][fn][i2 * 2 + 1] + __ldg(bias + o + 1);
                __nv_bfloat162 p = __floats2bfloat162_rn(v0, v1);
                *(uint32_t*)(dsm + ml * 272 + ol * 2) = *(uint32_t*)&p;
            }
        }
    __syncthreads();

    int row = threadIdx.x >> 1, half = threadIdx.x & 1;
    size_t t = (size_t)m0 + row;
    __nv_bfloat16* dst = g_qkv_bf + (size_t)branch * QKV_HALF + t * 384 + n0 + half * 64;
    const char* src = dsm + row * 272 + half * 128;
    #pragma unroll
    for (int j = 0; j < 8; j++)
        *(uint4*)(dst + j * 8) = *(const uint4*)(src + j * 16);
}

// ---------------------------------------------------------------------------
// Attention: per (dir, b, head, line); reads token-major qkv, fp32 math.
// ---------------------------------------------------------------------------
__global__ __launch_bounds__(256) void attn_kernel()
{
    int id   = blockIdx.x;            // 0..2047
    int dir  = id >> 10;
    int b    = (id >> 9) & 1;
    int n    = (id >> 6) & 7;
    int l    = id & 63;

    int tid = threadIdx.x;
    int dd  = tid >> 2;               // 0..63 (the "other" spatial coord)
    int dq  = (tid & 3) * 4;          // head-dim offset 0,4,8,12

    const __nv_bfloat16* buf = g_qkv_bf + (size_t)dir * QKV_HALF;
    int hw = dir ? dd * 64 + l : l * 64 + dd;
    int oq = n * 16 + dq;

    float4 q[5], k[5];
    #pragma unroll
    for (int i = 0; i < 5; i++) {
        size_t t = ((size_t)(b * 5 + i) * 4096 + hw) * 384;
        uint2 rq = *reinterpret_cast<const uint2*>(buf + t + oq);
        uint2 rk = *reinterpret_cast<const uint2*>(buf + t + 128 + oq);
        float2 q0 = __bfloat1622float2(*reinterpret_cast<__nv_bfloat162*>(&rq.x));
        float2 q1 = __bfloat1622float2(*reinterpret_cast<__nv_bfloat162*>(&rq.y));
        float2 k0 = __bfloat1622float2(*reinterpret_cast<__nv_bfloat162*>(&rk.x));
        float2 k1 = __bfloat1622float2(*reinterpret_cast<__nv_bfloat162*>(&rk.y));
        q[i] = make_float4(q0.x, q0.y, q1.x, q1.y);
        k[i] = make_float4(k0.x, k0.y, k1.x, k1.y);
    }
    float p[25];
    #pragma unroll
    for (int i = 0; i < 5; i++)
        #pragma unroll
        for (int j = 0; j < 5; j++) {
            float4 a = q[i], c = k[j];
            p[i*5+j] = a.x*c.x + a.y*c.y + a.z*c.z + a.w*c.w;
        }

    __shared__ float red[25][8];
    #pragma unroll
    for (int e = 0; e < 25; e++) {
        float v = p[e];
        #pragma unroll
        for (int off = 16; off; off >>= 1) v += __shfl_down_sync(0xffffffffu, v, off);
        if ((tid & 31) == 0) red[e][tid >> 5] = v;
    }
    __syncthreads();

    __shared__ float P[5][5];
    if (tid < 5) {
        float srow[5];
        float mx = -1e30f;
        #pragma unroll
        for (int j = 0; j < 5; j++) {
            float s = 0.f;
            #pragma unroll
            for (int wdx = 0; wdx < 8; wdx++) s += red[tid*5+j][wdx];
            s *= (1.f / 32.f);
            srow[j] = s; mx = fmaxf(mx, s);
        }
        float se = 0.f;
        #pragma unroll
        for (int j = 0; j < 5; j++) { srow[j] = __expf(srow[j] - mx); se += srow[j]; }
        float inv = 1.f / se;
        #pragma unroll
        for (int j = 0; j < 5; j++) P[tid][j] = srow[j] * inv;
    }
    __syncthreads();

    float4 o[5];
    #pragma unroll
    for (int i = 0; i < 5; i++) o[i] = make_float4(0.f, 0.f, 0.f, 0.f);
    #pragma unroll
    for (int j = 0; j < 5; j++) {
        size_t t = ((size_t)(b * 5 + j) * 4096 + hw) * 384;
        uint2 rv = *reinterpret_cast<const uint2*>(buf + t + 256 + oq);
        float2 v0 = __bfloat1622float2(*reinterpret_cast<__nv_bfloat162*>(&rv.x));
        float2 v1 = __bfloat1622float2(*reinterpret_cast<__nv_bfloat162*>(&rv.y));
        #pragma unroll
        for (int i = 0; i < 5; i++) {
            float pij = P[i][j];
            o[i].x = fmaf(pij, v0.x, o[i].x);
            o[i].y = fmaf(pij, v0.y, o[i].y);
            o[i].z = fmaf(pij, v1.x, o[i].z);
            o[i].w = fmaf(pij, v1.y, o[i].w);
        }
    }

    int c = dir ? (128 + n * 16 + dq) : (n * 16 + dq);
    #pragma unroll
    for (int fi = 0; fi < 5; fi++) {
        size_t tok = (size_t)(b * 5 + fi) * 4096 + hw;
        __nv_bfloat162 lo = __floats2bfloat162_rn(o[fi].x, o[fi].y);
        __nv_bfloat162 hi = __floats2bfloat162_rn(o[fi].z, o[fi].w);
        uint2 packed;
        packed.x = *reinterpret_cast<uint32_t*>(&lo);
        packed.y = *reinterpret_cast<uint32_t*>(&hi);
        *reinterpret_cast<uint2*>(g_ao_bf + tok * 256 + c) = packed;
    }
}

// ---------------------------------------------------------------------------
// Output projection + residual: y = ao @ wf^T + bf + x (fp32 token-major)
// ---------------------------------------------------------------------------
__global__ __launch_bounds__(256) void proj_mm(const float* __restrict__ bfp)
{
    extern __shared__ char dsm[];
    int m0 = blockIdx.y * 128, n0 = blockIdx.x * 128;

    float acc[4][4][4];
    wgemm(g_ao_bf, 256, g_wf, 256, m0, n0, 4, dsm, acc);

    // stage residual fp32 tile [m][o], stride 132 floats (coalesced load)
    float* Rs = reinterpret_cast<float*>(dsm);
    {
        int tid = threadIdx.x;
        #pragma unroll
        for (int it = 0; it < 16; it++) {
            int idx = it * 256 + tid;
            int r = idx >> 5, c4 = idx & 31;
            float4 v = *reinterpret_cast<const float4*>(
                g_xT + (size_t)(m0 + r) * 256 + n0 + c4 * 4);
            *reinterpret_cast<float4*>(Rs + r * 132 + c4 * 4) = v;
        }
    }
    __syncthreads();

    const int lane = threadIdx.x & 31, w = threadIdx.x >> 5;
    const int wm = (w & 1) * 64, wn = (w >> 1) * 32;
    const int g = lane >> 2, tq = lane & 3;
    #pragma unroll
    for (int fm = 0; fm < 4; fm++)
        #pragma unroll
        for (int i2 = 0; i2 < 2; i2++) {
            int ml = wm + fm * 16 + g + i2 * 8;
            #pragma unroll
            for (int fn = 0; fn < 4; fn++) {
                int ol = wn + fn * 8 + tq * 2;
                int o  = n0 + ol;
                Rs[ml * 132 + ol]     += acc[fm][fn][i2 * 2]     + __ldg(bfp + o);
                Rs[ml * 132 + ol + 1] += acc[fm][fn][i2 * 2 + 1] + __ldg(bfp + o + 1);
            }
        }
    __syncthreads();

    int row = threadIdx.x >> 1, half = threadIdx.x & 1;
    float* dst = g_y + (size_t)(m0 + row) * 256 + n0 + half * 64;
    const float* src = Rs + row * 132 + half * 64;
    #pragma unroll
    for (int j = 0; j < 16; j++)
        *reinterpret_cast<float4*>(dst + j * 4) = *reinterpret_cast<const float4*>(src + j * 4);
}

// ---------------------------------------------------------------------------
// LN2: g_y (fp32) -> g_tn_bf (bf16). One warp per token.
// ---------------------------------------------------------------------------
__global__ __launch_bounds__(256) void ln2_kernel(
    const float* __restrict__ gam, const float* __restrict__ bet)
{
    int t    = blockIdx.x * 8 + (threadIdx.x >> 5);
    int lane = threadIdx.x & 31;
    const float* row = g_y + (size_t)t * 256;
    int c = lane * 4;

    float4 v0 = *reinterpret_cast<const float4*>(row + c);
    float4 v1 = *reinterpret_cast<const float4*>(row + 128 + c);
    float s  = v0.x + v0.y + v0.z + v0.w + v1.x + v1.y + v1.z + v1.w;
    float sq = v0.x*v0.x + v0.y*v0.y + v0.z*v0.z + v0.w*v0.w
             + v1.x*v1.x + v1.y*v1.y + v1.z*v1.z + v1.w*v1.w;
    #pragma unroll
    for (int off = 16; off; off >>= 1) {
        s  += __shfl_xor_sync(0xffffffffu, s,  off);
        sq += __shfl_xor_sync(0xffffffffu, sq, off);
    }
    float m = s * (1.f / 256.f);
    float r = rsqrtf(sq * (1.f / 256.f) - m * m + 1e-5f);

    __nv_bfloat16* out = g_tn_bf + (size_t)t * 256;
    float4 g0 = *reinterpret_cast<const float4*>(gam + c);
    float4 b0 = *reinterpret_cast<const float4*>(bet + c);
    float4 g1 = *reinterpret_cast<const float4*>(gam + 128 + c);
    float4 b1 = *reinterpret_cast<const float4*>(bet + 128 + c);
    __nv_bfloat162 p0 = __floats2bfloat162_rn((v0.x-m)*r*g0.x+b0.x, (v0.y-m)*r*g0.y+b0.y);
    __nv_bfloat162 p1 = __floats2bfloat162_rn((v0.z-m)*r*g0.z+b0.z, (v0.w-m)*r*g0.w+b0.w);
    __nv_bfloat162 p2 = __floats2bfloat162_rn((v1.x-m)*r*g1.x+b1.x, (v1.y-m)*r*g1.y+b1.y);
    __nv_bfloat162 p3 = __floats2bfloat162_rn((v1.z-m)*r*g1.z+b1.z, (v1.w-m)*r*g1.w+b1.w);
    uint2 u0, u1;
    u0.x = *reinterpret_cast<uint32_t*>(&p0);
    u0.y = *reinterpret_cast<uint32_t*>(&p1);
    u1.x = *reinterpret_cast<uint32_t*>(&p2);
    u1.y = *reinterpret_cast<uint32_t*>(&p3);
    *reinterpret_cast<uint2*>(out + c)       = u0;
    *reinterpret_cast<uint2*>(out + 128 + c) = u1;
}

// ---------------------------------------------------------------------------
// MLP GEMM1 + exact GELU -> g_hid_bf (bf16 token-major)
// ---------------------------------------------------------------------------
__global__ __launch_bounds__(256) void mlp1_mm(const float* __restrict__ b1)
{
    extern __shared__ char dsm[];
    int m0 = blockIdx.y * 128, n0 = blockIdx.x * 128;

    float acc[4][4][4];
    wgemm(g_tn_bf, 256, g_w1, 256, m0, n0, 4, dsm, acc);

    const int lane = threadIdx.x & 31, w = threadIdx.x >> 5;
    const int wm = (w & 1) * 64, wn = (w >> 1) * 32;
    const int g = lane >> 2, tq = lane & 3;
    #pragma unroll
    for (int fm = 0; fm < 4; fm++)
        #pragma unroll
        for (int i2 = 0; i2 < 2; i2++) {
            int ml = wm + fm * 16 + g + i2 * 8;
            #pragma unroll
            for (int fn = 0; fn < 4; fn++) {
                int ol = wn + fn * 8 + tq * 2;
                int o  = n0 + ol;
                float h0 = acc[fm][fn][i2 * 2]     + __ldg(b1 + o);
                float h1 = acc[fm][fn][i2 * 2 + 1] + __ldg(b1 + o + 1);
                float gl0 = 0.5f * h0 * (1.f + erff(h0 * 0.70710678118654752f));
                float gl1 = 0.5f * h1 * (1.f + erff(h1 * 0.70710678118654752f));
                __nv_bfloat162 p = __floats2bfloat162_rn(gl0, gl1);
                *(uint32_t*)(dsm + ml * 272 + ol * 2) = *(uint32_t*)&p;
            }
        }
    __syncthreads();

    int row = threadIdx.x >> 1, half = threadIdx.x & 1;
    __nv_bfloat16* dst = g_hid_bf + (size_t)(m0 + row) * 1024 + n0 + half * 64;
    const char* src = dsm + row * 272 + half * 128;
    #pragma unroll
    for (int j = 0; j < 8; j++)
        *(uint4*)(dst + j * 8) = *(const uint4*)(src + j * 16);
}

// ---------------------------------------------------------------------------
// MLP GEMM2 + residual + transposed store to out (B,F,C,H,W)
// ---------------------------------------------------------------------------
__global__ __launch_bounds__(256) void mlp2_mm(
    const float* __restrict__ b2, float* __restrict__ out)
{
    extern __shared__ char dsm[];
    int m0 = blockIdx.y * 128, n0 = blockIdx.x * 128;

    float acc[4][4][4];
    wgemm(g_hid_bf, 1024, g_w2, 1024, m0, n0, 16, dsm, acc);

    float* Rs = reinterpret_cast<float*>(dsm);
    {
        int tid = threadIdx.x;
        #pragma unroll
        for (int it = 0; it < 16; it++) {
            int idx = it * 256 + tid;
            int r = idx >> 5, c4 = idx & 31;
            float4 v = *reinterpret_cast<const float4*>(
                g_y + (size_t)(m0 + r) * 256 + n0 + c4 * 4);
            *reinterpret_cast<float4*>(Rs + r * 132 + c4 * 4) = v;
        }
    }
    __syncthreads();

    const int lane = threadIdx.x & 31, w = threadIdx.x >> 5;
    const int wm = (w & 1) * 64, wn = (w >> 1) * 32;
    const int g = lane >> 2, tq = lane & 3;
    #pragma unroll
    for (int fm = 0; fm < 4; fm++)
        #pragma unroll
        for (int i2 = 0; i2 < 2; i2++) {
            int ml = wm + fm * 16 + g + i2 * 8;
            #pragma unroll
            for (int fn = 0; fn < 4; fn++) {
                int ol = wn + fn * 8 + tq * 2;
                int o  = n0 + ol;
                Rs[ml * 132 + ol]     += acc[fm][fn][i2 * 2]     + __ldg(b2 + o);
                Rs[ml * 132 + ol + 1] += acc[fm][fn][i2 * 2 + 1] + __ldg(b2 + o + 1);
            }
        }
    __syncthreads();

    // transposed coalesced write: fixed channel o -> 128 consecutive hw
    int bfi = m0 >> 12, hw0 = m0 & 4095;
    int o = threadIdx.x >> 1, half = threadIdx.x & 1;
    float* dst = out + ((size_t)bfi * 256 + n0 + o) * 4096 + hw0 + half * 64;
    #pragma unroll
    for (int j = 0; j < 16; j++) {
        int mb = half * 64 + j * 4;
        float4 v;
        v.x = Rs[(mb + 0) * 132 + o];
        v.y = Rs[(mb + 1) * 132 + o];
        v.z = Rs[(mb + 2) * 132 + o];
        v.w = Rs[(mb + 3) * 132 + o];
        *reinterpret_cast<float4*>(dst + j * 4) = v;
    }
}

// ---------------------------------------------------------------------------
extern "C" void kernel_launch(void* const* d_in, const int* in_sizes, int n_in,
                              void* d_out, int out_size)
{
    const float* x     = (const float*)d_in[0];
    const float* ln1_g = (const float*)d_in[1];
    const float* ln1_b = (const float*)d_in[2];
    const float* wh    = (const float*)d_in[3];
    const float* bh    = (const float*)d_in[4];
    const float* wv    = (const float*)d_in[5];
    const float* bv    = (const float*)d_in[6];
    const float* wf    = (const float*)d_in[7];
    const float* bf    = (const float*)d_in[8];
    const float* ln2_g = (const float*)d_in[9];
    const float* ln2_b = (const float*)d_in[10];
    const float* w1    = (const float*)d_in[11];
    const float* b1    = (const float*)d_in[12];
    const float* w2    = (const float*)d_in[13];
    const float* b2    = (const float*)d_in[14];
    float* out = (float*)d_out;

    static bool attr_done = false;
    if (!attr_done) {
        cudaFuncSetAttribute(qkv_mm,  cudaFuncAttributeMaxDynamicSharedMemorySize, SMEM_DYN);
        cudaFuncSetAttribute(proj_mm, cudaFuncAttributeMaxDynamicSharedMemorySize, SMEM_DYN);
        cudaFuncSetAttribute(mlp1_mm, cudaFuncAttributeMaxDynamicSharedMemorySize, SMEM_DYN);
        cudaFuncSetAttribute(mlp2_mm, cudaFuncAttributeMaxDynamicSharedMemorySize, SMEM_DYN);
        attr_done = true;
    }

    __nv_bfloat16 *dwh, *dwv, *dwf, *dw1, *dw2;
    cudaGetSymbolAddress((void**)&dwh, g_wh);
    cudaGetSymbolAddress((void**)&dwv, g_wv);
    cudaGetSymbolAddress((void**)&dwf, g_wf);
    cudaGetSymbolAddress((void**)&dw1, g_w1);
    cudaGetSymbolAddress((void**)&dw2, g_w2);
    cvt_kernel<<<(384*128 + 255) / 256, 256>>>(wh, dwh, 384*128);
    cvt_kernel<<<(384*128 + 255) / 256, 256>>>(wv, dwv, 384*128);
    cvt_kernel<<<(256*256 + 255) / 256, 256>>>(wf, dwf, 256*256);
    cvt_kernel<<<(1024*256 + 255) / 256, 256>>>(w1, dw1, 1024*256);
    cvt_kernel<<<(256*1024 + 255) / 256, 256>>>(w2, dw2, 256*1024);

    ln1_kernel<<<dim3(128, 10), 256>>>(x, ln1_g, ln1_b);
    qkv_mm    <<<dim3(3, 320, 2), 256, SMEM_DYN>>>(bh, bv);
    attn_kernel<<<2048, 256>>>();
    proj_mm   <<<dim3(2, 320), 256, SMEM_DYN>>>(bf);
    ln2_kernel<<<5120, 256>>>(ln2_g, ln2_b);
    mlp1_mm   <<<dim3(8, 320), 256, SMEM_DYN>>>(b1);
    mlp2_mm   <<<dim3(2, 320), 256, SMEM_DYN>>>(b2, out);
}

// round 4
// speedup vs baseline: 4.7579x; 1.2037x over previous
#include <cuda_runtime.h>
#include <cuda_bf16.h>
#include <math.h>
#include <cstdint>

// ---------------------------------------------------------------------------
// Problem constants
// ---------------------------------------------------------------------------
#define HWS  4096         // H*W
#define TOK  40960        // B*F*H*W
#define QKV_HALF (TOK*384)

// ---------------------------------------------------------------------------
// Static device scratch
// ---------------------------------------------------------------------------
__device__ __nv_bfloat16 g_xn_bf [TOK*256];    // LN1 out (bf16, token-major)
__device__ __nv_bfloat16 g_qkv_bf[2*QKV_HALF]; // qkv token-major [branch][t][384]
__device__ __nv_bfloat16 g_ao_bf [TOK*256];    // attention out (bf16 token-major)
__device__ float         g_y     [TOK*256];    // y = proj + x (fp32)
__device__ __nv_bfloat16 g_tn_bf [TOK*256];    // LN2 out (bf16)
__device__ __nv_bfloat16 g_hid_bf[TOK*1024];   // MLP hidden (bf16)
// bf16 weight copies
__device__ __nv_bfloat16 g_wh[384*128];
__device__ __nv_bfloat16 g_wv[384*128];
__device__ __nv_bfloat16 g_wf[256*256];
__device__ __nv_bfloat16 g_w1[1024*256];
__device__ __nv_bfloat16 g_w2[256*1024];

#define SMEM_SWIZZLE_128B(byte_offset) \
    ((byte_offset) ^ (((byte_offset) >> 3) & 0x70))

// Dynamic smem: 3 cp.async stages x (16KB A + 16KB B) = 96KB.
// Epilogue reuse: fp32 tile [128][132] = 67584B, bf16 tile [128][136] = 34816B.
#define SMEM_DYN 98304

// ---------------------------------------------------------------------------
// Baseline-ISA building blocks (all legal at compute_103)
// ---------------------------------------------------------------------------
__device__ __forceinline__ void mma16816(float d[4], const uint32_t a[4],
                                         uint32_t b0, uint32_t b1)
{
    asm volatile(
        "mma.sync.aligned.m16n8k16.row.col.f32.bf16.bf16.f32 "
        "{%0,%1,%2,%3},{%4,%5,%6,%7},{%8,%9},{%0,%1,%2,%3};"
        : "+f"(d[0]), "+f"(d[1]), "+f"(d[2]), "+f"(d[3])
        : "r"(a[0]), "r"(a[1]), "r"(a[2]), "r"(a[3]), "r"(b0), "r"(b1));
}
__device__ __forceinline__ void ldsm_x4(uint32_t r[4], uint32_t addr)
{
    asm volatile("ldmatrix.sync.aligned.m8n8.x4.shared.b16 {%0,%1,%2,%3}, [%4];"
        : "=r"(r[0]), "=r"(r[1]), "=r"(r[2]), "=r"(r[3]) : "r"(addr));
}
__device__ __forceinline__ void cp_async16(uint32_t saddr, const void* g)
{
    asm volatile("cp.async.cg.shared.global [%0], [%1], 16;" :: "r"(saddr), "l"(g));
}
__device__ __forceinline__ void cp_commit()
{
    asm volatile("cp.async.commit_group;");
}
template<int N> __device__ __forceinline__ void cp_wait()
{
    asm volatile("cp.async.wait_group %0;" :: "n"(N));
}
__device__ __forceinline__ uint32_t smem_u32(const void* p)
{
    uint32_t a;
    asm("{ .reg .u64 t; cvta.to.shared.u64 t, %1; cvt.u32.u64 %0, t; }"
        : "=r"(a) : "l"(p));
    return a;
}

// ---------------------------------------------------------------------------
// Warp-MMA GEMM: acc[fm][fn][4] += A[m0+*,k] * B[n0+*,k]^T, bf16 in fp32 out.
// Tile 128x128, 8 warps (warp tile 64m x 32n), K chunks of 64 elems.
// 3-stage cp.async pipeline, ldmatrix fragment loads.
// Frag owner: g = lane>>2, tq = lane&3.
//   acc[fm][fn][i]: m = wm+fm*16+g+8*(i>>1), n = wn+fn*8+tq*2+(i&1)
// ---------------------------------------------------------------------------
__device__ __forceinline__ void wgemm(
    const __nv_bfloat16* __restrict__ A, int lda,
    const __nv_bfloat16* __restrict__ B, int ldb,
    int m0, int n0, int nchunks, uint32_t sbase,
    float (&acc)[4][4][4])
{
    const int tid  = threadIdx.x;
    const int lane = tid & 31;
    const int w    = tid >> 5;
    const int wm   = (w & 1) * 64;
    const int wn   = (w >> 1) * 32;
    const int r_ld = tid >> 3;       // 0..31
    const int cc_ld = tid & 7;       // 16B chunk within 128B row

    // ldmatrix per-lane row/col selects
    const int a_row = (lane & 7) + ((lane >> 3) & 1) * 8;  // 0..15 within frag
    const int a_k16 = ((lane >> 4) & 1) * 16;              // +16B for k8..15
    const int b_row = (lane & 7) + ((lane >> 4) & 1) * 8;  // n within 16-row pair
    const int b_k16 = ((lane >> 3) & 1) * 16;

    #pragma unroll
    for (int fm = 0; fm < 4; fm++)
        #pragma unroll
        for (int fn = 0; fn < 4; fn++)
            #pragma unroll
            for (int i = 0; i < 4; i++) acc[fm][fn][i] = 0.f;

    auto issue = [&](int c) {
        int s = c % 3;
        int k0 = c << 6;
        uint32_t base = sbase + s * 32768;
        uint32_t off = SMEM_SWIZZLE_128B((uint32_t)(r_ld * 128 + cc_ld * 16));
        #pragma unroll
        for (int it = 0; it < 4; it++) {
            int r = it * 32 + r_ld;
            cp_async16(base + it * 4096 + off,
                       A + (size_t)(m0 + r) * lda + k0 + cc_ld * 8);
            cp_async16(base + 16384 + it * 4096 + off,
                       B + (size_t)(n0 + r) * ldb + k0 + cc_ld * 8);
        }
        cp_commit();
    };

    issue(0);
    if (nchunks > 1) issue(1);

    for (int c = 0; c < nchunks; c++) {
        if (c + 2 < nchunks) { issue(c + 2); cp_wait<2>(); }
        else if (c + 1 < nchunks) cp_wait<1>();
        else cp_wait<0>();
        __syncthreads();

        uint32_t Ab = sbase + (c % 3) * 32768;
        uint32_t Bb = Ab + 16384;
        #pragma unroll
        for (int ks = 0; ks < 4; ks++) {
            int kb = ks * 32;
            uint32_t a[4][4];
            #pragma unroll
            for (int fm = 0; fm < 4; fm++) {
                int r = wm + fm * 16 + a_row;
                ldsm_x4(a[fm], Ab + SMEM_SWIZZLE_128B((uint32_t)(r * 128 + kb + a_k16)));
            }
            uint32_t bfr[2][4];
            #pragma unroll
            for (int fp = 0; fp < 2; fp++) {
                int rn = wn + fp * 16 + b_row;
                ldsm_x4(bfr[fp], Bb + SMEM_SWIZZLE_128B((uint32_t)(rn * 128 + kb + b_k16)));
            }
            #pragma unroll
            for (int fn = 0; fn < 4; fn++) {
                uint32_t b0 = bfr[fn >> 1][(fn & 1) * 2];
                uint32_t b1 = bfr[fn >> 1][(fn & 1) * 2 + 1];
                #pragma unroll
                for (int fm = 0; fm < 4; fm++)
                    mma16816(acc[fm][fn], a[fm], b0, b1);
            }
        }
        __syncthreads();
    }
}

// ---------------------------------------------------------------------------
// LN1: x (B,F,C,H,W) -> g_xn_bf (bf16 token-major)
// ---------------------------------------------------------------------------
__global__ __launch_bounds__(256) void ln1_kernel(
    const float* __restrict__ x,
    const float* __restrict__ gam,
    const float* __restrict__ bet)
{
    __shared__ float sm[256][33];
    __shared__ float psum[8][32], psq[8][32];
    __shared__ float mu[32], rs[32];

    int bf  = blockIdx.y;
    int hw0 = blockIdx.x * 32;
    int tid = threadIdx.x;
    int tx  = tid & 31, ty = tid >> 5;

    const float* xp = x + (size_t)bf * 256 * HWS;
    #pragma unroll
    for (int c0 = 0; c0 < 256; c0 += 8) {
        int c = c0 + ty;
        sm[c][tx] = xp[(size_t)c * HWS + hw0 + tx];
    }
    __syncthreads();

    float s = 0.f, sq = 0.f;
    #pragma unroll
    for (int k = 0; k < 32; k++) {
        float v = sm[ty * 32 + k][tx];
        s += v; sq += v * v;
    }
    psum[ty][tx] = s; psq[ty][tx] = sq;
    __syncthreads();

    if (ty == 0) {
        float S = 0.f, Q = 0.f;
        #pragma unroll
        for (int k = 0; k < 8; k++) { S += psum[k][tx]; Q += psq[k][tx]; }
        float m   = S * (1.f / 256.f);
        float var = Q * (1.f / 256.f) - m * m;
        mu[tx] = m;
        rs[tx] = rsqrtf(var + 1e-5f);
    }
    __syncthreads();

    int tokl = tid >> 3, cg = tid & 7;
    int tok  = bf * HWS + hw0 + tokl;
    float m = mu[tokl], r = rs[tokl];
    size_t rowoff = (size_t)tok * 256;
    #pragma unroll
    for (int k = 0; k < 32; k++) {
        int c = k * 8 + cg;
        float v = sm[c][tokl];
        g_xn_bf[rowoff + c] = __float2bfloat16_rn((v - m) * r * gam[c] + bet[c]);
    }
}

// ---------------------------------------------------------------------------
// Single weight-conversion kernel (all 5 weights)
// ---------------------------------------------------------------------------
__global__ __launch_bounds__(256) void cvt_all(
    const float* __restrict__ wh, const float* __restrict__ wv,
    const float* __restrict__ wf, const float* __restrict__ w1,
    const float* __restrict__ w2)
{
    int i = blockIdx.x * 256 + threadIdx.x;
    if (i < 49152)        g_wh[i]          = __float2bfloat16_rn(wh[i]);
    else if (i < 98304)   g_wv[i - 49152]  = __float2bfloat16_rn(wv[i - 49152]);
    else if (i < 163840)  g_wf[i - 98304]  = __float2bfloat16_rn(wf[i - 98304]);
    else if (i < 425984)  g_w1[i - 163840] = __float2bfloat16_rn(w1[i - 163840]);
    else if (i < 688128)  g_w2[i - 425984] = __float2bfloat16_rn(w2[i - 425984]);
}

// ---------------------------------------------------------------------------
// QKV GEMM -> token-major g_qkv_bf[branch][t][384]
// ---------------------------------------------------------------------------
__global__ __launch_bounds__(256, 2) void qkv_mm(
    const float* __restrict__ bh, const float* __restrict__ bv)
{
    extern __shared__ __align__(1024) char dsm[];
    uint32_t sbase = smem_u32(dsm);
    int branch = blockIdx.z;
    int m0 = blockIdx.y * 128, n0 = blockIdx.x * 128;
    const __nv_bfloat16* A = g_xn_bf + branch * 128;
    const __nv_bfloat16* W = branch ? g_wv : g_wh;
    const float* bias = branch ? bv : bh;

    float acc[4][4][4];
    wgemm(A, 256, W, 128, m0, n0, 2, sbase, acc);

    // stage bf16 tile [m][o], stride 136 bf16 (272B rows)
    const int lane = threadIdx.x & 31, w = threadIdx.x >> 5;
    const int wm = (w & 1) * 64, wn = (w >> 1) * 32;
    const int g = lane >> 2, tq = lane & 3;
    #pragma unroll
    for (int fm = 0; fm < 4; fm++)
        #pragma unroll
        for (int i2 = 0; i2 < 2; i2++) {
            int ml = wm + fm * 16 + g + i2 * 8;
            #pragma unroll
            for (int fn = 0; fn < 4; fn++) {
                int ol = wn + fn * 8 + tq * 2;
                int o  = n0 + ol;
                float v0 = acc[fm][fn][i2 * 2]     + __ldg(bias + o);
                float v1 = acc[fm][fn][i2 * 2 + 1] + __ldg(bias + o + 1);
                __nv_bfloat162 p = __floats2bfloat162_rn(v0, v1);
                *(uint32_t*)(dsm + ml * 272 + ol * 2) = *(uint32_t*)&p;
            }
        }
    __syncthreads();

    int row = threadIdx.x >> 1, half = threadIdx.x & 1;
    size_t t = (size_t)m0 + row;
    __nv_bfloat16* dst = g_qkv_bf + (size_t)branch * QKV_HALF + t * 384 + n0 + half * 64;
    const char* src = dsm + row * 272 + half * 128;
    #pragma unroll
    for (int j = 0; j < 8; j++)
        *(uint4*)(dst + j * 8) = *(const uint4*)(src + j * 16);
}

// ---------------------------------------------------------------------------
// Attention: per (dir, b, head, line); reads token-major qkv, fp32 math.
// ---------------------------------------------------------------------------
__global__ __launch_bounds__(256) void attn_kernel()
{
    int id   = blockIdx.x;            // 0..2047
    int dir  = id >> 10;
    int b    = (id >> 9) & 1;
    int n    = (id >> 6) & 7;
    int l    = id & 63;

    int tid = threadIdx.x;
    int dd  = tid >> 2;               // 0..63 (the "other" spatial coord)
    int dq  = (tid & 3) * 4;          // head-dim offset 0,4,8,12

    const __nv_bfloat16* buf = g_qkv_bf + (size_t)dir * QKV_HALF;
    int hw = dir ? dd * 64 + l : l * 64 + dd;
    int oq = n * 16 + dq;

    float4 q[5], k[5];
    #pragma unroll
    for (int i = 0; i < 5; i++) {
        size_t t = ((size_t)(b * 5 + i) * 4096 + hw) * 384;
        uint2 rq = *reinterpret_cast<const uint2*>(buf + t + oq);
        uint2 rk = *reinterpret_cast<const uint2*>(buf + t + 128 + oq);
        float2 q0 = __bfloat1622float2(*reinterpret_cast<__nv_bfloat162*>(&rq.x));
        float2 q1 = __bfloat1622float2(*reinterpret_cast<__nv_bfloat162*>(&rq.y));
        float2 k0 = __bfloat1622float2(*reinterpret_cast<__nv_bfloat162*>(&rk.x));
        float2 k1 = __bfloat1622float2(*reinterpret_cast<__nv_bfloat162*>(&rk.y));
        q[i] = make_float4(q0.x, q0.y, q1.x, q1.y);
        k[i] = make_float4(k0.x, k0.y, k1.x, k1.y);
    }
    float p[25];
    #pragma unroll
    for (int i = 0; i < 5; i++)
        #pragma unroll
        for (int j = 0; j < 5; j++) {
            float4 a = q[i], c = k[j];
            p[i*5+j] = a.x*c.x + a.y*c.y + a.z*c.z + a.w*c.w;
        }

    __shared__ float red[25][8];
    #pragma unroll
    for (int e = 0; e < 25; e++) {
        float v = p[e];
        #pragma unroll
        for (int off = 16; off; off >>= 1) v += __shfl_down_sync(0xffffffffu, v, off);
        if ((tid & 31) == 0) red[e][tid >> 5] = v;
    }
    __syncthreads();

    __shared__ float P[5][5];
    if (tid < 5) {
        float srow[5];
        float mx = -1e30f;
        #pragma unroll
        for (int j = 0; j < 5; j++) {
            float s = 0.f;
            #pragma unroll
            for (int wdx = 0; wdx < 8; wdx++) s += red[tid*5+j][wdx];
            s *= (1.f / 32.f);
            srow[j] = s; mx = fmaxf(mx, s);
        }
        float se = 0.f;
        #pragma unroll
        for (int j = 0; j < 5; j++) { srow[j] = __expf(srow[j] - mx); se += srow[j]; }
        float inv = 1.f / se;
        #pragma unroll
        for (int j = 0; j < 5; j++) P[tid][j] = srow[j] * inv;
    }
    __syncthreads();

    float4 o[5];
    #pragma unroll
    for (int i = 0; i < 5; i++) o[i] = make_float4(0.f, 0.f, 0.f, 0.f);
    #pragma unroll
    for (int j = 0; j < 5; j++) {
        size_t t = ((size_t)(b * 5 + j) * 4096 + hw) * 384;
        uint2 rv = *reinterpret_cast<const uint2*>(buf + t + 256 + oq);
        float2 v0 = __bfloat1622float2(*reinterpret_cast<__nv_bfloat162*>(&rv.x));
        float2 v1 = __bfloat1622float2(*reinterpret_cast<__nv_bfloat162*>(&rv.y));
        #pragma unroll
        for (int i = 0; i < 5; i++) {
            float pij = P[i][j];
            o[i].x = fmaf(pij, v0.x, o[i].x);
            o[i].y = fmaf(pij, v0.y, o[i].y);
            o[i].z = fmaf(pij, v1.x, o[i].z);
            o[i].w = fmaf(pij, v1.y, o[i].w);
        }
    }

    int c = dir ? (128 + n * 16 + dq) : (n * 16 + dq);
    #pragma unroll
    for (int fi = 0; fi < 5; fi++) {
        size_t tok = (size_t)(b * 5 + fi) * 4096 + hw;
        __nv_bfloat162 lo = __floats2bfloat162_rn(o[fi].x, o[fi].y);
        __nv_bfloat162 hi = __floats2bfloat162_rn(o[fi].z, o[fi].w);
        uint2 packed;
        packed.x = *reinterpret_cast<uint32_t*>(&lo);
        packed.y = *reinterpret_cast<uint32_t*>(&hi);
        *reinterpret_cast<uint2*>(g_ao_bf + tok * 256 + c) = packed;
    }
}

// ---------------------------------------------------------------------------
// Output projection + residual: y = ao @ wf^T + bf + x (fp32 token-major)
// Residual read directly from x (B,F,C,H,W): coalesced along hw, transposed
// into smem.
// ---------------------------------------------------------------------------
__global__ __launch_bounds__(256, 2) void proj_mm(
    const float* __restrict__ x, const float* __restrict__ bfp)
{
    extern __shared__ __align__(1024) char dsm[];
    uint32_t sbase = smem_u32(dsm);
    int m0 = blockIdx.y * 128, n0 = blockIdx.x * 128;

    float acc[4][4][4];
    wgemm(g_ao_bf, 256, g_wf, 256, m0, n0, 4, sbase, acc);

    // stage residual from x: tile is (tokens m0..m0+127 = one bf, contiguous hw)
    float* Rs = reinterpret_cast<float*>(dsm);
    {
        int bfi = m0 >> 12, hw0 = m0 & 4095;
        int tid = threadIdx.x;
        #pragma unroll
        for (int it = 0; it < 16; it++) {
            int idx = it * 256 + tid;
            int c = idx >> 5, hw4 = idx & 31;
            float4 v = *reinterpret_cast<const float4*>(
                x + ((size_t)bfi * 256 + n0 + c) * 4096 + hw0 + hw4 * 4);
            Rs[(hw4 * 4 + 0) * 132 + c] = v.x;
            Rs[(hw4 * 4 + 1) * 132 + c] = v.y;
            Rs[(hw4 * 4 + 2) * 132 + c] = v.z;
            Rs[(hw4 * 4 + 3) * 132 + c] = v.w;
        }
    }
    __syncthreads();

    const int lane = threadIdx.x & 31, w = threadIdx.x >> 5;
    const int wm = (w & 1) * 64, wn = (w >> 1) * 32;
    const int g = lane >> 2, tq = lane & 3;
    #pragma unroll
    for (int fm = 0; fm < 4; fm++)
        #pragma unroll
        for (int i2 = 0; i2 < 2; i2++) {
            int ml = wm + fm * 16 + g + i2 * 8;
            #pragma unroll
            for (int fn = 0; fn < 4; fn++) {
                int ol = wn + fn * 8 + tq * 2;
                int o  = n0 + ol;
                Rs[ml * 132 + ol]     += acc[fm][fn][i2 * 2]     + __ldg(bfp + o);
                Rs[ml * 132 + ol + 1] += acc[fm][fn][i2 * 2 + 1] + __ldg(bfp + o + 1);
            }
        }
    __syncthreads();

    int row = threadIdx.x >> 1, half = threadIdx.x & 1;
    float* dst = g_y + (size_t)(m0 + row) * 256 + n0 + half * 64;
    const float* src = Rs + row * 132 + half * 64;
    #pragma unroll
    for (int j = 0; j < 16; j++)
        *reinterpret_cast<float4*>(dst + j * 4) = *reinterpret_cast<const float4*>(src + j * 4);
}

// ---------------------------------------------------------------------------
// LN2: g_y (fp32) -> g_tn_bf (bf16). One warp per token.
// ---------------------------------------------------------------------------
__global__ __launch_bounds__(256) void ln2_kernel(
    const float* __restrict__ gam, const float* __restrict__ bet)
{
    int t    = blockIdx.x * 8 + (threadIdx.x >> 5);
    int lane = threadIdx.x & 31;
    const float* row = g_y + (size_t)t * 256;
    int c = lane * 4;

    float4 v0 = *reinterpret_cast<const float4*>(row + c);
    float4 v1 = *reinterpret_cast<const float4*>(row + 128 + c);
    float s  = v0.x + v0.y + v0.z + v0.w + v1.x + v1.y + v1.z + v1.w;
    float sq = v0.x*v0.x + v0.y*v0.y + v0.z*v0.z + v0.w*v0.w
             + v1.x*v1.x + v1.y*v1.y + v1.z*v1.z + v1.w*v1.w;
    #pragma unroll
    for (int off = 16; off; off >>= 1) {
        s  += __shfl_xor_sync(0xffffffffu, s,  off);
        sq += __shfl_xor_sync(0xffffffffu, sq, off);
    }
    float m = s * (1.f / 256.f);
    float r = rsqrtf(sq * (1.f / 256.f) - m * m + 1e-5f);

    __nv_bfloat16* out = g_tn_bf + (size_t)t * 256;
    float4 g0 = *reinterpret_cast<const float4*>(gam + c);
    float4 b0 = *reinterpret_cast<const float4*>(bet + c);
    float4 g1 = *reinterpret_cast<const float4*>(gam + 128 + c);
    float4 b1 = *reinterpret_cast<const float4*>(bet + 128 + c);
    __nv_bfloat162 p0 = __floats2bfloat162_rn((v0.x-m)*r*g0.x+b0.x, (v0.y-m)*r*g0.y+b0.y);
    __nv_bfloat162 p1 = __floats2bfloat162_rn((v0.z-m)*r*g0.z+b0.z, (v0.w-m)*r*g0.w+b0.w);
    __nv_bfloat162 p2 = __floats2bfloat162_rn((v1.x-m)*r*g1.x+b1.x, (v1.y-m)*r*g1.y+b1.y);
    __nv_bfloat162 p3 = __floats2bfloat162_rn((v1.z-m)*r*g1.z+b1.z, (v1.w-m)*r*g1.w+b1.w);
    uint2 u0, u1;
    u0.x = *reinterpret_cast<uint32_t*>(&p0);
    u0.y = *reinterpret_cast<uint32_t*>(&p1);
    u1.x = *reinterpret_cast<uint32_t*>(&p2);
    u1.y = *reinterpret_cast<uint32_t*>(&p3);
    *reinterpret_cast<uint2*>(out + c)       = u0;
    *reinterpret_cast<uint2*>(out + 128 + c) = u1;
}

// ---------------------------------------------------------------------------
// MLP GEMM1 + exact GELU -> g_hid_bf (bf16 token-major)
// ---------------------------------------------------------------------------
__global__ __launch_bounds__(256, 2) void mlp1_mm(const float* __restrict__ b1)
{
    extern __shared__ __align__(1024) char dsm[];
    uint32_t sbase = smem_u32(dsm);
    int m0 = blockIdx.y * 128, n0 = blockIdx.x * 128;

    float acc[4][4][4];
    wgemm(g_tn_bf, 256, g_w1, 256, m0, n0, 4, sbase, acc);

    const int lane = threadIdx.x & 31, w = threadIdx.x >> 5;
    const int wm = (w & 1) * 64, wn = (w >> 1) * 32;
    const int g = lane >> 2, tq = lane & 3;
    #pragma unroll
    for (int fm = 0; fm < 4; fm++)
        #pragma unroll
        for (int i2 = 0; i2 < 2; i2++) {
            int ml = wm + fm * 16 + g + i2 * 8;
            #pragma unroll
            for (int fn = 0; fn < 4; fn++) {
                int ol = wn + fn * 8 + tq * 2;
                int o  = n0 + ol;
                float h0 = acc[fm][fn][i2 * 2]     + __ldg(b1 + o);
                float h1 = acc[fm][fn][i2 * 2 + 1] + __ldg(b1 + o + 1);
                float gl0 = 0.5f * h0 * (1.f + erff(h0 * 0.70710678118654752f));
                float gl1 = 0.5f * h1 * (1.f + erff(h1 * 0.70710678118654752f));
                __nv_bfloat162 p = __floats2bfloat162_rn(gl0, gl1);
                *(uint32_t*)(dsm + ml * 272 + ol * 2) = *(uint32_t*)&p;
            }
        }
    __syncthreads();

    int row = threadIdx.x >> 1, half = threadIdx.x & 1;
    __nv_bfloat16* dst = g_hid_bf + (size_t)(m0 + row) * 1024 + n0 + half * 64;
    const char* src = dsm + row * 272 + half * 128;
    #pragma unroll
    for (int j = 0; j < 8; j++)
        *(uint4*)(dst + j * 8) = *(const uint4*)(src + j * 16);
}

// ---------------------------------------------------------------------------
// MLP GEMM2 + residual + transposed store to out (B,F,C,H,W)
// ---------------------------------------------------------------------------
__global__ __launch_bounds__(256, 2) void mlp2_mm(
    const float* __restrict__ b2, float* __restrict__ out)
{
    extern __shared__ __align__(1024) char dsm[];
    uint32_t sbase = smem_u32(dsm);
    int m0 = blockIdx.y * 128, n0 = blockIdx.x * 128;

    float acc[4][4][4];
    wgemm(g_hid_bf, 1024, g_w2, 1024, m0, n0, 16, sbase, acc);

    float* Rs = reinterpret_cast<float*>(dsm);
    {
        int tid = threadIdx.x;
        #pragma unroll
        for (int it = 0; it < 16; it++) {
            int idx = it * 256 + tid;
            int r = idx >> 5, c4 = idx & 31;
            float4 v = *reinterpret_cast<const float4*>(
                g_y + (size_t)(m0 + r) * 256 + n0 + c4 * 4);
            *reinterpret_cast<float4*>(Rs + r * 132 + c4 * 4) = v;
        }
    }
    __syncthreads();

    const int lane = threadIdx.x & 31, w = threadIdx.x >> 5;
    const int wm = (w & 1) * 64, wn = (w >> 1) * 32;
    const int g = lane >> 2, tq = lane & 3;
    #pragma unroll
    for (int fm = 0; fm < 4; fm++)
        #pragma unroll
        for (int i2 = 0; i2 < 2; i2++) {
            int ml = wm + fm * 16 + g + i2 * 8;
            #pragma unroll
            for (int fn = 0; fn < 4; fn++) {
                int ol = wn + fn * 8 + tq * 2;
                int o  = n0 + ol;
                Rs[ml * 132 + ol]     += acc[fm][fn][i2 * 2]     + __ldg(b2 + o);
                Rs[ml * 132 + ol + 1] += acc[fm][fn][i2 * 2 + 1] + __ldg(b2 + o + 1);
            }
        }
    __syncthreads();

    // transposed coalesced write: fixed channel o -> 128 consecutive hw
    int bfi = m0 >> 12, hw0 = m0 & 4095;
    int o = threadIdx.x >> 1, half = threadIdx.x & 1;
    float* dst = out + ((size_t)bfi * 256 + n0 + o) * 4096 + hw0 + half * 64;
    #pragma unroll
    for (int j = 0; j < 16; j++) {
        int mb = half * 64 + j * 4;
        float4 v;
        v.x = Rs[(mb + 0) * 132 + o];
        v.y = Rs[(mb + 1) * 132 + o];
        v.z = Rs[(mb + 2) * 132 + o];
        v.w = Rs[(mb + 3) * 132 + o];
        *reinterpret_cast<float4*>(dst + j * 4) = v;
    }
}

// ---------------------------------------------------------------------------
extern "C" void kernel_launch(void* const* d_in, const int* in_sizes, int n_in,
                              void* d_out, int out_size)
{
    const float* x     = (const float*)d_in[0];
    const float* ln1_g = (const float*)d_in[1];
    const float* ln1_b = (const float*)d_in[2];
    const float* wh    = (const float*)d_in[3];
    const float* bh    = (const float*)d_in[4];
    const float* wv    = (const float*)d_in[5];
    const float* bv    = (const float*)d_in[6];
    const float* wf    = (const float*)d_in[7];
    const float* bf    = (const float*)d_in[8];
    const float* ln2_g = (const float*)d_in[9];
    const float* ln2_b = (const float*)d_in[10];
    const float* w1    = (const float*)d_in[11];
    const float* b1    = (const float*)d_in[12];
    const float* w2    = (const float*)d_in[13];
    const float* b2    = (const float*)d_in[14];
    float* out = (float*)d_out;

    cudaFuncSetAttribute(qkv_mm,  cudaFuncAttributeMaxDynamicSharedMemorySize, SMEM_DYN);
    cudaFuncSetAttribute(proj_mm, cudaFuncAttributeMaxDynamicSharedMemorySize, SMEM_DYN);
    cudaFuncSetAttribute(mlp1_mm, cudaFuncAttributeMaxDynamicSharedMemorySize, SMEM_DYN);
    cudaFuncSetAttribute(mlp2_mm, cudaFuncAttributeMaxDynamicSharedMemorySize, SMEM_DYN);

    cvt_all<<<2688, 256>>>(wh, wv, wf, w1, w2);
    ln1_kernel<<<dim3(128, 10), 256>>>(x, ln1_g, ln1_b);
    qkv_mm    <<<dim3(3, 320, 2), 256, SMEM_DYN>>>(bh, bv);
    attn_kernel<<<2048, 256>>>();
    proj_mm   <<<dim3(2, 320), 256, SMEM_DYN>>>(x, bf);
    ln2_kernel<<<5120, 256>>>(ln2_g, ln2_b);
    mlp1_mm   <<<dim3(8, 320), 256, SMEM_DYN>>>(b1);
    mlp2_mm   <<<dim3(2, 320), 256, SMEM_DYN>>>(b2, out);
}